// round 15
// baseline (speedup 1.0000x reference)
#include <cuda_runtime.h>

typedef unsigned long long u64;
typedef unsigned int u32;

#define HW (512*512)

// ---------------- device scratch ----------------
__device__ u32 g_maxbits;   // zero-init; k_scale's last block re-zeroes it each call
__device__ u32 g_ctr;       // completion counter for k_scale's last-block reset

// ---------------- packed f32x2 helpers ----------------
__device__ __forceinline__ u64 pk2(float lo, float hi) {
    u64 r;
    asm("mov.b64 %0, {%1, %2};" : "=l"(r) : "r"(__float_as_uint(lo)), "r"(__float_as_uint(hi)));
    return r;
}
__device__ __forceinline__ void unpk2(u64 v, float& lo, float& hi) {
    u32 a, b;
    asm("mov.b64 {%0, %1}, %2;" : "=r"(a), "=r"(b) : "l"(v));
    lo = __uint_as_float(a); hi = __uint_as_float(b);
}
__device__ __forceinline__ u64 dup2(float x) { return pk2(x, x); }
__device__ __forceinline__ u64 fma2_(u64 a, u64 b, u64 c) {
    u64 d; asm("fma.rn.f32x2 %0, %1, %2, %3;" : "=l"(d) : "l"(a), "l"(b), "l"(c)); return d;
}
__device__ __forceinline__ u64 mul2_(u64 a, u64 b) {
    u64 d; asm("mul.rn.f32x2 %0, %1, %2;" : "=l"(d) : "l"(a), "l"(b)); return d;
}
// packed relu: bits(relu(x)) == max_s32(bits(x), 0)
__device__ __forceinline__ u64 relu2(u64 s) {
    u32 lo, hi;
    asm("mov.b64 {%0,%1}, %2;" : "=r"(lo), "=r"(hi) : "l"(s));
    asm("max.s32 %0, %0, 0;" : "+r"(lo));
    asm("max.s32 %0, %0, 0;" : "+r"(hi));
    u64 r;
    asm("mov.b64 %0, {%1,%2};" : "=l"(r) : "r"(lo), "r"(hi));
    return r;
}
// packed running-max (halves of m >= 0, so s32 max == float max)
__device__ __forceinline__ u64 max2_s32(u64 m, u64 s) {
    u32 ml, mh, sl, sh;
    asm("mov.b64 {%0,%1}, %2;" : "=r"(ml), "=r"(mh) : "l"(m));
    asm("mov.b64 {%0,%1}, %2;" : "=r"(sl), "=r"(sh) : "l"(s));
    asm("max.s32 %0, %0, %1;" : "+r"(ml) : "r"(sl));
    asm("max.s32 %0, %0, %1;" : "+r"(mh) : "r"(sh));
    u64 r;
    asm("mov.b64 %0, {%1,%2};" : "=l"(r) : "r"(ml), "r"(mh));
    return r;
}

// ---------------- per-pixel normal prep ----------------
__device__ __forceinline__ void load_normal(const float* __restrict__ nptr,
                                            float& nx, float& ny, float& nz) {
    float c0 = nptr[0], c1 = nptr[1], c2 = nptr[2];
    nx = (c2 - 0.5f) * 2.0f;
    ny = (c1 - 0.5f) * 2.0f;
    nz = (c0 - 0.5f) * 2.0f;
    float nn = sqrtf(nx * nx + ny * ny + nz * nz);
    float iv = 1.0f / fmaxf(nn, 1e-12f);
    nx *= iv; ny *= iv; nz *= iv;
}

// ---------------- kernel 1: fused table-build + UNSCALED shade + max ----------
// Table: per m-pair mp (240; eh>=1 lights only), 16 floats (64B):
//   [hx0,hx1, hy0,hy1, hz0,hz1, wr0,wr1, wg0,wg1, wb0,wb1, pad x4]
// w = env * sin(phi) / 60; built per block from env (only 16 phi + 32 theta trig).
// The 32 eh=0 lights have w == 0 exactly; their direction h=(0,1,1)/sqrt2 enters
// the global max analytically. Shade accumulates sum(relu(s)^64 * w) UNSCALED
// and tracks max(s); k_scale applies 1/max^64 afterwards.
__global__ void __launch_bounds__(256, 2) k_shade(const float* __restrict__ env,
                                                  const float* __restrict__ normal,
                                                  float* __restrict__ out) {
    __shared__ float4 tab[960];   // 15KB table for this batch
    __shared__ float ssp[16], scp[16], sst[32], sct[32];
    __shared__ float wm[8];
    int b = blockIdx.y;

    // phase 1: the 48 distinct trig values
    {
        int t = threadIdx.x;
        const float PI_F = 3.14159274101257324e+00f;
        if (t < 16) {
            float phi = ((float)t * (1.0f / 16.0f)) * PI_F;
            ssp[t] = sinf(phi);
            scp[t] = cosf(phi);
        } else if (t >= 32 && t < 64) {
            int ew = t - 32;
            float th = (((float)ew * (1.0f / 32.0f)) * 2.0f) * PI_F;
            sst[ew] = sinf(th);
            sct[ew] = cosf(th);
        }
    }
    __syncthreads();

    // phase 2: build the 240-pair table for this batch (same math as old k_setup)
    {
        const float SC = (float)(1.0 / 60.0);
        for (int m = 32 + threadIdx.x; m < 512; m += 256) {
            int eh = m >> 5, ew = m & 31;
            float sp = ssp[eh], cp = scp[eh], st = sst[ew], ct = sct[ew];
            float hx = st * sp;
            float hy = cp;
            float hz = 1.0f - ct * sp;
            float nrm = sqrtf(hx * hx + hy * hy + hz * hz);
            float rin = 1.0f / nrm;
            hx *= rin; hy *= rin; hz *= rin;

            int i = m - 32, mp = i >> 1, half = i & 1;
            float sw = sp * SC;
            float* row = (float*)tab + mp * 16;
            row[0 + half]  = hx;
            row[2 + half]  = hy;
            row[4 + half]  = hz;
            const float* e = env + (b * 512 + m) * 3;
            row[6 + half]  = e[0] * sw;
            row[8 + half]  = e[1] * sw;
            row[10 + half] = e[2] * sw;
        }
    }
    __syncthreads();

    int i0 = blockIdx.x * 256 + threadIdx.x;     // 0..131071 within batch
    int i1 = i0 + 131072;

    float ax, ay, az, bx, by, bz;
    load_normal(normal + (b * HW + i0) * 3, ax, ay, az);
    load_normal(normal + (b * HW + i1) * 3, bx, by, bz);
    u64 ax2 = dup2(ax), ay2 = dup2(ay), az2 = dup2(az);
    u64 bx2 = dup2(bx), by2 = dup2(by), bz2 = dup2(bz);

    u64 ar0 = 0ull, ag0 = 0ull, ab0 = 0ull;
    u64 ar1 = 0ull, ag1 = 0ull, ab1 = 0ull;
    u64 ma = 0ull, mb = 0ull;                    // packed running max of s

    #pragma unroll 8
    for (int mp = 0; mp < 240; ++mp) {
        float4 q0 = tab[mp * 4 + 0];
        float4 q1 = tab[mp * 4 + 1];
        float4 q2 = tab[mp * 4 + 2];
        u64 hx01 = pk2(q0.x, q0.y), hy01 = pk2(q0.z, q0.w), hz01 = pk2(q1.x, q1.y);
        u64 wr01 = pk2(q1.z, q1.w), wg01 = pk2(q2.x, q2.y), wb01 = pk2(q2.z, q2.w);

        // pixel 0
        u64 sa = fma2_(ax2, hx01, fma2_(ay2, hy01, mul2_(az2, hz01)));
        ma = max2_s32(ma, sa);                   // ALU pipe, spare issue slots
        u64 ua = relu2(sa);
        u64 ca = mul2_(ua, ua);          // ^2
        ca = mul2_(ca, ca);              // ^4
        ca = mul2_(ca, ca);              // ^8
        ca = mul2_(ca, ca);              // ^16
        ca = mul2_(ca, ca);              // ^32
        ca = mul2_(ca, ca);              // ^64
        ar0 = fma2_(ca, wr01, ar0);
        ag0 = fma2_(ca, wg01, ag0);
        ab0 = fma2_(ca, wb01, ab0);

        // pixel 1
        u64 sb = fma2_(bx2, hx01, fma2_(by2, hy01, mul2_(bz2, hz01)));
        mb = max2_s32(mb, sb);
        u64 ub = relu2(sb);
        u64 cb = mul2_(ub, ub);
        cb = mul2_(cb, cb);
        cb = mul2_(cb, cb);
        cb = mul2_(cb, cb);
        cb = mul2_(cb, cb);
        cb = mul2_(cb, cb);
        ar1 = fma2_(cb, wr01, ar1);
        ag1 = fma2_(cb, wg01, ag1);
        ab1 = fma2_(cb, wb01, ab1);
    }

    // unscaled outputs
    float r0, r1, g0, g1, bb0, bb1;
    int ob = b * 3 * HW;
    unpk2(ar0, r0, r1); unpk2(ag0, g0, g1); unpk2(ab0, bb0, bb1);
    out[ob + i0]          = r0 + r1;
    out[ob + HW + i0]     = g0 + g1;
    out[ob + 2 * HW + i0] = bb0 + bb1;
    unpk2(ar1, r0, r1); unpk2(ag1, g0, g1); unpk2(ab1, bb0, bb1);
    out[ob + i1]          = r0 + r1;
    out[ob + HW + i1]     = g0 + g1;
    out[ob + 2 * HW + i1] = bb0 + bb1;

    // global-max reduction (include analytic eh=0 light h=(0,1,1)/sqrt2)
    const float R2I = 0.70710678118654752f;
    float l0, h0, l1, h1;
    unpk2(ma, l0, h0); unpk2(mb, l1, h1);
    float mx = fmaxf(fmaxf(fmaxf(l0, h0), fmaxf(l1, h1)),
                     fmaxf(fmaxf((ay + az) * R2I, (by + bz) * R2I), 0.0f));
    #pragma unroll
    for (int o = 16; o; o >>= 1) mx = fmaxf(mx, __shfl_xor_sync(0xffffffffu, mx, o));
    if ((threadIdx.x & 31) == 0) wm[threadIdx.x >> 5] = mx;
    __syncthreads();
    if (threadIdx.x == 0) {
        float m2 = wm[0];
        #pragma unroll
        for (int i = 1; i < 8; ++i) m2 = fmaxf(m2, wm[i]);
        atomicMax(&g_maxbits, __float_as_uint(m2));  // nonneg bits monotone as uint
    }
}

// ---------------- kernel 2: scale epilogue + state reset ----------------
// out *= 1/gm^64 (same 6-squaring sequence as shade's power). Last finishing
// block zeroes g_maxbits and g_ctr so every kernel_launch call starts clean.
// Safety of the reset: each block reads gm, then __syncthreads, then thread 0
// bumps the counter; the reset fires only after ALL 1536 counter bumps, i.e.
// after every block's gm read. Deterministic across calls.
__global__ void k_scale(float* __restrict__ out) {
    float gm = __uint_as_float(g_maxbits);
    float g2 = gm * gm;            // ^2
    g2 = g2 * g2;                  // ^4
    g2 = g2 * g2;                  // ^8
    g2 = g2 * g2;                  // ^16
    g2 = g2 * g2;                  // ^32
    g2 = g2 * g2;                  // ^64
    float inv = 1.0f / g2;

    int i = blockIdx.x * 256 + threadIdx.x;      // grid 1536 -> 393216 float4
    float4* o4 = (float4*)out;
    float4 v = o4[i];
    v.x *= inv; v.y *= inv; v.z *= inv; v.w *= inv;
    o4[i] = v;

    __syncthreads();                             // all threads have read gm & stored
    if (threadIdx.x == 0) {
        __threadfence();
        u32 done = atomicAdd(&g_ctr, 1u);
        if (done == gridDim.x - 1u) {            // last block: reset state
            g_maxbits = 0u;
            g_ctr = 0u;
        }
    }
}

// ---------------- launch ----------------
extern "C" void kernel_launch(void* const* d_in, const int* in_sizes, int n_in,
                              void* d_out, int out_size) {
    const float* env    = (const float*)d_in[0];
    const float* normal = (const float*)d_in[1];
    if (n_in >= 2 && in_sizes[0] > in_sizes[1]) {
        env    = (const float*)d_in[1];
        normal = (const float*)d_in[0];
    }
    k_shade<<<dim3(512, 2), 256>>>(env, normal, (float*)d_out);
    k_scale<<<1536, 256>>>((float*)d_out);
}

// round 16
// speedup vs baseline: 1.0374x; 1.0374x over previous
#include <cuda_runtime.h>

typedef unsigned long long u64;
typedef unsigned int u32;

#define HW (512*512)

// ---------------- device scratch ----------------
// Shade table: per batch b (2), per m-pair mp (240; eh>=1 lights only), 16 floats (64B):
//   [hx0,hx1, hy0,hy1, hz0,hz1, wr0,wr1, wg0,wg1, wb0,wb1, pad x4]
// w = env * sin(phi) / 60.  The 32 eh=0 lights have w == 0 exactly -> dropped from shade
// (their direction h=(0,1,1)/sqrt2 still participates in the global max, analytically).
__device__ __align__(16) float g_table[2 * 240 * 16];
__device__ u32 g_maxbits;

// ---------------- packed f32x2 helpers ----------------
__device__ __forceinline__ u64 pk2(float lo, float hi) {
    u64 r;
    asm("mov.b64 %0, {%1, %2};" : "=l"(r) : "r"(__float_as_uint(lo)), "r"(__float_as_uint(hi)));
    return r;
}
__device__ __forceinline__ void unpk2(u64 v, float& lo, float& hi) {
    u32 a, b;
    asm("mov.b64 {%0, %1}, %2;" : "=r"(a), "=r"(b) : "l"(v));
    lo = __uint_as_float(a); hi = __uint_as_float(b);
}
__device__ __forceinline__ u64 dup2(float x) { return pk2(x, x); }
__device__ __forceinline__ u64 fma2_(u64 a, u64 b, u64 c) {
    u64 d; asm("fma.rn.f32x2 %0, %1, %2, %3;" : "=l"(d) : "l"(a), "l"(b), "l"(c)); return d;
}
__device__ __forceinline__ u64 mul2_(u64 a, u64 b) {
    u64 d; asm("mul.rn.f32x2 %0, %1, %2;" : "=l"(d) : "l"(a), "l"(b)); return d;
}
// packed relu: bits(relu(x)) == max_s32(bits(x), 0)
__device__ __forceinline__ u64 relu2(u64 s) {
    u32 lo, hi;
    asm("mov.b64 {%0,%1}, %2;" : "=r"(lo), "=r"(hi) : "l"(s));
    asm("max.s32 %0, %0, 0;" : "+r"(lo));
    asm("max.s32 %0, %0, 0;" : "+r"(hi));
    u64 r;
    asm("mov.b64 %0, {%1,%2};" : "=l"(r) : "r"(lo), "r"(hi));
    return r;
}
// packed running-max (halves of m >= 0, so s32 max == float max)
__device__ __forceinline__ u64 max2_s32(u64 m, u64 s) {
    u32 ml, mh, sl, sh;
    asm("mov.b64 {%0,%1}, %2;" : "=r"(ml), "=r"(mh) : "l"(m));
    asm("mov.b64 {%0,%1}, %2;" : "=r"(sl), "=r"(sh) : "l"(s));
    asm("max.s32 %0, %0, %1;" : "+r"(ml) : "r"(sl));
    asm("max.s32 %0, %0, %1;" : "+r"(mh) : "r"(sh));
    u64 r;
    asm("mov.b64 %0, {%1,%2};" : "=l"(r) : "r"(ml), "r"(mh));
    return r;
}

// ---------------- kernel 0: constants + table + scratch reset ----------------
// 4 blocks x 256 threads: one (batch, light) per thread -> trig spread over 4 SMs.
__global__ void k_setup(const float* __restrict__ env) {
    int tid = blockIdx.x * 256 + threadIdx.x;    // 0..1023
    if (tid == 0) g_maxbits = 0u;
    int m = tid & 511;                           // light index
    int b = tid >> 9;                            // batch

    int eh = m >> 5, ew = m & 31;
    const float PI_F = 3.14159274101257324e+00f;
    float phi = ((float)eh * (1.0f / 16.0f)) * PI_F;
    float th  = (((float)ew * (1.0f / 32.0f)) * 2.0f) * PI_F;

    float sp = sinf(phi), cp = cosf(phi);
    float st = sinf(th),  ct = cosf(th);

    // l = (st*sp, cp, -ct*sp); v = (0,0,1); h = normalize(v + l)
    float hx = st * sp;
    float hy = cp;
    float hz = 1.0f - ct * sp;
    float nrm = sqrtf(hx * hx + hy * hy + hz * hz);
    float rin = 1.0f / nrm;
    hx *= rin; hy *= rin; hz *= rin;

    if (m >= 32) {                    // eh>=1: 480 lights -> 240 pairs
        int i = m - 32, mp = i >> 1, half = i & 1;
        const float SC = (float)(1.0 / 60.0);
        float sw = sp * SC;

        float* row = g_table + (b * 240 + mp) * 16;
        row[0 + half]  = hx;
        row[2 + half]  = hy;
        row[4 + half]  = hz;
        const float* e = env + (b * 512 + m) * 3;
        row[6 + half]  = e[0] * sw;
        row[8 + half]  = e[1] * sw;
        row[10 + half] = e[2] * sw;
        if (half == 0) { row[12] = 0.f; row[13] = 0.f; row[14] = 0.f; row[15] = 0.f; }
    }
}

// ---------------- per-pixel normal prep ----------------
__device__ __forceinline__ void load_normal(const float* __restrict__ nptr,
                                            float& nx, float& ny, float& nz) {
    float c0 = nptr[0], c1 = nptr[1], c2 = nptr[2];
    nx = (c2 - 0.5f) * 2.0f;
    ny = (c1 - 0.5f) * 2.0f;
    nz = (c0 - 0.5f) * 2.0f;
    float nn = sqrtf(nx * nx + ny * ny + nz * nz);
    float iv = 1.0f / fmaxf(nn, 1e-12f);
    nx *= iv; ny *= iv; nz *= iv;
}

// ---------------- kernel 1: fused UNSCALED shade + global-max tracking --------
// 2 pixels/thread, 240 pairs. Accumulates sum(relu(s)^64 * w) without the 1/max
// normalization; tracks max(s) in spare ALU issue slots.
__global__ void __launch_bounds__(256, 2) k_shade(const float* __restrict__ normal,
                                                  float* __restrict__ out) {
    __shared__ float4 tab[960];   // 15KB table for this batch
    __shared__ float wm[8];
    int b = blockIdx.y;
    const float4* gt = (const float4*)g_table + b * 960;
    for (int i = threadIdx.x; i < 960; i += 256) tab[i] = gt[i];
    __syncthreads();

    int i0 = blockIdx.x * 256 + threadIdx.x;     // 0..131071 within batch
    int i1 = i0 + 131072;

    float ax, ay, az, bx, by, bz;
    load_normal(normal + (b * HW + i0) * 3, ax, ay, az);
    load_normal(normal + (b * HW + i1) * 3, bx, by, bz);
    u64 ax2 = dup2(ax), ay2 = dup2(ay), az2 = dup2(az);
    u64 bx2 = dup2(bx), by2 = dup2(by), bz2 = dup2(bz);

    u64 ar0 = 0ull, ag0 = 0ull, ab0 = 0ull;
    u64 ar1 = 0ull, ag1 = 0ull, ab1 = 0ull;
    u64 ma = 0ull, mb = 0ull;                    // packed running max of s

    #pragma unroll 8
    for (int mp = 0; mp < 240; ++mp) {
        float4 q0 = tab[mp * 4 + 0];
        float4 q1 = tab[mp * 4 + 1];
        float4 q2 = tab[mp * 4 + 2];
        u64 hx01 = pk2(q0.x, q0.y), hy01 = pk2(q0.z, q0.w), hz01 = pk2(q1.x, q1.y);
        u64 wr01 = pk2(q1.z, q1.w), wg01 = pk2(q2.x, q2.y), wb01 = pk2(q2.z, q2.w);

        // pixel 0
        u64 sa = fma2_(ax2, hx01, fma2_(ay2, hy01, mul2_(az2, hz01)));
        ma = max2_s32(ma, sa);                   // ALU pipe, spare issue slots
        u64 ua = relu2(sa);
        u64 ca = mul2_(ua, ua);          // ^2
        ca = mul2_(ca, ca);              // ^4
        ca = mul2_(ca, ca);              // ^8
        ca = mul2_(ca, ca);              // ^16
        ca = mul2_(ca, ca);              // ^32
        ca = mul2_(ca, ca);              // ^64
        ar0 = fma2_(ca, wr01, ar0);
        ag0 = fma2_(ca, wg01, ag0);
        ab0 = fma2_(ca, wb01, ab0);

        // pixel 1
        u64 sb = fma2_(bx2, hx01, fma2_(by2, hy01, mul2_(bz2, hz01)));
        mb = max2_s32(mb, sb);
        u64 ub = relu2(sb);
        u64 cb = mul2_(ub, ub);
        cb = mul2_(cb, cb);
        cb = mul2_(cb, cb);
        cb = mul2_(cb, cb);
        cb = mul2_(cb, cb);
        cb = mul2_(cb, cb);
        ar1 = fma2_(cb, wr01, ar1);
        ag1 = fma2_(cb, wg01, ag1);
        ab1 = fma2_(cb, wb01, ab1);
    }

    // unscaled outputs
    float r0, r1, g0, g1, bb0, bb1;
    int ob = b * 3 * HW;
    unpk2(ar0, r0, r1); unpk2(ag0, g0, g1); unpk2(ab0, bb0, bb1);
    out[ob + i0]          = r0 + r1;
    out[ob + HW + i0]     = g0 + g1;
    out[ob + 2 * HW + i0] = bb0 + bb1;
    unpk2(ar1, r0, r1); unpk2(ag1, g0, g1); unpk2(ab1, bb0, bb1);
    out[ob + i1]          = r0 + r1;
    out[ob + HW + i1]     = g0 + g1;
    out[ob + 2 * HW + i1] = bb0 + bb1;

    // global-max reduction (include analytic eh=0 light h=(0,1,1)/sqrt2)
    const float R2I = 0.70710678118654752f;
    float l0, h0, l1, h1;
    unpk2(ma, l0, h0); unpk2(mb, l1, h1);
    float mx = fmaxf(fmaxf(fmaxf(l0, h0), fmaxf(l1, h1)),
                     fmaxf(fmaxf((ay + az) * R2I, (by + bz) * R2I), 0.0f));
    #pragma unroll
    for (int o = 16; o; o >>= 1) mx = fmaxf(mx, __shfl_xor_sync(0xffffffffu, mx, o));
    if ((threadIdx.x & 31) == 0) wm[threadIdx.x >> 5] = mx;
    __syncthreads();
    if (threadIdx.x == 0) {
        float m2 = wm[0];
        #pragma unroll
        for (int i = 1; i < 8; ++i) m2 = fmaxf(m2, wm[i]);
        atomicMax(&g_maxbits, __float_as_uint(m2));  // nonneg bits monotone as uint
    }
}

// ---------------- kernel 2: scale epilogue: out *= 1/gm^64 ----------------
// 4 float4 per thread (MLP=4): grid 384 x 256 threads x 4 tiles = 393216 float4.
__global__ void k_scale(float* __restrict__ out) {
    float gm = __uint_as_float(g_maxbits);
    float g2 = gm * gm;            // ^2
    g2 = g2 * g2;                  // ^4
    g2 = g2 * g2;                  // ^8
    g2 = g2 * g2;                  // ^16
    g2 = g2 * g2;                  // ^32
    g2 = g2 * g2;                  // ^64
    float inv = 1.0f / g2;

    float4* o4 = (float4*)out;
    int base = blockIdx.x * 1024 + threadIdx.x;  // 4 coalesced 256-wide tiles
    float4 v0 = o4[base];
    float4 v1 = o4[base + 256];
    float4 v2 = o4[base + 512];
    float4 v3 = o4[base + 768];
    v0.x *= inv; v0.y *= inv; v0.z *= inv; v0.w *= inv;
    v1.x *= inv; v1.y *= inv; v1.z *= inv; v1.w *= inv;
    v2.x *= inv; v2.y *= inv; v2.z *= inv; v2.w *= inv;
    v3.x *= inv; v3.y *= inv; v3.z *= inv; v3.w *= inv;
    o4[base]       = v0;
    o4[base + 256] = v1;
    o4[base + 512] = v2;
    o4[base + 768] = v3;
}

// ---------------- launch ----------------
extern "C" void kernel_launch(void* const* d_in, const int* in_sizes, int n_in,
                              void* d_out, int out_size) {
    const float* env    = (const float*)d_in[0];
    const float* normal = (const float*)d_in[1];
    if (n_in >= 2 && in_sizes[0] > in_sizes[1]) {
        env    = (const float*)d_in[1];
        normal = (const float*)d_in[0];
    }
    k_setup<<<4, 256>>>(env);
    k_shade<<<dim3(512, 2), 256>>>(normal, (float*)d_out);
    k_scale<<<384, 256>>>((float*)d_out);
}

// round 17
// speedup vs baseline: 1.0467x; 1.0090x over previous
#include <cuda_runtime.h>

typedef unsigned long long u64;
typedef unsigned int u32;

#define HW (512*512)

// ---------------- device scratch ----------------
// Shade table: per batch b (2), per m-pair mp (240; eh>=1 lights only), 16 floats (64B):
//   [hx0,hx1, hy0,hy1, hz0,hz1, wr0,wr1, wg0,wg1, wb0,wb1, pad x4]
// w = env * sin(phi) / 60.  The 32 eh=0 lights have w == 0 exactly -> dropped from shade
// (their direction h=(0,1,1)/sqrt2 still participates in the global max, analytically).
__device__ __align__(16) float g_table[2 * 240 * 16];
__device__ u32 g_maxbits;

// ---------------- packed f32x2 helpers ----------------
__device__ __forceinline__ u64 pk2(float lo, float hi) {
    u64 r;
    asm("mov.b64 %0, {%1, %2};" : "=l"(r) : "r"(__float_as_uint(lo)), "r"(__float_as_uint(hi)));
    return r;
}
__device__ __forceinline__ void unpk2(u64 v, float& lo, float& hi) {
    u32 a, b;
    asm("mov.b64 {%0, %1}, %2;" : "=r"(a), "=r"(b) : "l"(v));
    lo = __uint_as_float(a); hi = __uint_as_float(b);
}
__device__ __forceinline__ u64 dup2(float x) { return pk2(x, x); }
__device__ __forceinline__ u64 fma2_(u64 a, u64 b, u64 c) {
    u64 d; asm("fma.rn.f32x2 %0, %1, %2, %3;" : "=l"(d) : "l"(a), "l"(b), "l"(c)); return d;
}
__device__ __forceinline__ u64 mul2_(u64 a, u64 b) {
    u64 d; asm("mul.rn.f32x2 %0, %1, %2;" : "=l"(d) : "l"(a), "l"(b)); return d;
}
// packed relu: bits(relu(x)) == max_s32(bits(x), 0)
__device__ __forceinline__ u64 relu2(u64 s) {
    u32 lo, hi;
    asm("mov.b64 {%0,%1}, %2;" : "=r"(lo), "=r"(hi) : "l"(s));
    asm("max.s32 %0, %0, 0;" : "+r"(lo));
    asm("max.s32 %0, %0, 0;" : "+r"(hi));
    u64 r;
    asm("mov.b64 %0, {%1,%2};" : "=l"(r) : "r"(lo), "r"(hi));
    return r;
}
// packed running-max (halves of m >= 0, so s32 max == float max)
__device__ __forceinline__ u64 max2_s32(u64 m, u64 s) {
    u32 ml, mh, sl, sh;
    asm("mov.b64 {%0,%1}, %2;" : "=r"(ml), "=r"(mh) : "l"(m));
    asm("mov.b64 {%0,%1}, %2;" : "=r"(sl), "=r"(sh) : "l"(s));
    asm("max.s32 %0, %0, %1;" : "+r"(ml) : "r"(sl));
    asm("max.s32 %0, %0, %1;" : "+r"(mh) : "r"(sh));
    u64 r;
    asm("mov.b64 %0, {%1,%2};" : "=l"(r) : "r"(ml), "r"(mh));
    return r;
}

// ---------------- kernel 0: constants + table + scratch reset ----------------
// 16 blocks x 64 threads: one (batch, light) per thread, trig spread over 16 SMs.
__global__ void k_setup(const float* __restrict__ env) {
    int tid = blockIdx.x * 64 + threadIdx.x;     // 0..1023
    if (tid == 0) g_maxbits = 0u;
    int m = tid & 511;                           // light index
    int b = tid >> 9;                            // batch

    int eh = m >> 5, ew = m & 31;
    const float PI_F = 3.14159274101257324e+00f;
    float phi = ((float)eh * (1.0f / 16.0f)) * PI_F;
    float th  = (((float)ew * (1.0f / 32.0f)) * 2.0f) * PI_F;

    float sp = sinf(phi), cp = cosf(phi);
    float st = sinf(th),  ct = cosf(th);

    // l = (st*sp, cp, -ct*sp); v = (0,0,1); h = normalize(v + l)
    float hx = st * sp;
    float hy = cp;
    float hz = 1.0f - ct * sp;
    float nrm = sqrtf(hx * hx + hy * hy + hz * hz);
    float rin = 1.0f / nrm;
    hx *= rin; hy *= rin; hz *= rin;

    if (m >= 32) {                    // eh>=1: 480 lights -> 240 pairs
        int i = m - 32, mp = i >> 1, half = i & 1;
        const float SC = (float)(1.0 / 60.0);
        float sw = sp * SC;

        float* row = g_table + (b * 240 + mp) * 16;
        row[0 + half]  = hx;
        row[2 + half]  = hy;
        row[4 + half]  = hz;
        const float* e = env + (b * 512 + m) * 3;
        row[6 + half]  = e[0] * sw;
        row[8 + half]  = e[1] * sw;
        row[10 + half] = e[2] * sw;
        if (half == 0) { row[12] = 0.f; row[13] = 0.f; row[14] = 0.f; row[15] = 0.f; }
    }
}

// ---------------- per-pixel normal prep ----------------
__device__ __forceinline__ void load_normal(const float* __restrict__ nptr,
                                            float& nx, float& ny, float& nz) {
    float c0 = nptr[0], c1 = nptr[1], c2 = nptr[2];
    nx = (c2 - 0.5f) * 2.0f;
    ny = (c1 - 0.5f) * 2.0f;
    nz = (c0 - 0.5f) * 2.0f;
    float nn = sqrtf(nx * nx + ny * ny + nz * nz);
    float iv = 1.0f / fmaxf(nn, 1e-12f);
    nx *= iv; ny *= iv; nz *= iv;
}

// ---------------- kernel 1: fused UNSCALED shade + global-max tracking --------
// 2 pixels/thread, 240 pairs. Accumulates sum(relu(s)^64 * w) without the 1/max
// normalization; tracks max(s) in spare ALU issue slots.
__global__ void __launch_bounds__(256, 2) k_shade(const float* __restrict__ normal,
                                                  float* __restrict__ out) {
    __shared__ float4 tab[960];   // 15KB table for this batch
    __shared__ float wm[8];
    int b = blockIdx.y;
    const float4* gt = (const float4*)g_table + b * 960;
    for (int i = threadIdx.x; i < 960; i += 256) tab[i] = gt[i];
    __syncthreads();

    int i0 = blockIdx.x * 256 + threadIdx.x;     // 0..131071 within batch
    int i1 = i0 + 131072;

    float ax, ay, az, bx, by, bz;
    load_normal(normal + (b * HW + i0) * 3, ax, ay, az);
    load_normal(normal + (b * HW + i1) * 3, bx, by, bz);
    u64 ax2 = dup2(ax), ay2 = dup2(ay), az2 = dup2(az);
    u64 bx2 = dup2(bx), by2 = dup2(by), bz2 = dup2(bz);

    u64 ar0 = 0ull, ag0 = 0ull, ab0 = 0ull;
    u64 ar1 = 0ull, ag1 = 0ull, ab1 = 0ull;
    u64 ma = 0ull, mb = 0ull;                    // packed running max of s

    #pragma unroll 8
    for (int mp = 0; mp < 240; ++mp) {
        float4 q0 = tab[mp * 4 + 0];
        float4 q1 = tab[mp * 4 + 1];
        float4 q2 = tab[mp * 4 + 2];
        u64 hx01 = pk2(q0.x, q0.y), hy01 = pk2(q0.z, q0.w), hz01 = pk2(q1.x, q1.y);
        u64 wr01 = pk2(q1.z, q1.w), wg01 = pk2(q2.x, q2.y), wb01 = pk2(q2.z, q2.w);

        // pixel 0
        u64 sa = fma2_(ax2, hx01, fma2_(ay2, hy01, mul2_(az2, hz01)));
        ma = max2_s32(ma, sa);                   // ALU pipe, spare issue slots
        u64 ua = relu2(sa);
        u64 ca = mul2_(ua, ua);          // ^2
        ca = mul2_(ca, ca);              // ^4
        ca = mul2_(ca, ca);              // ^8
        ca = mul2_(ca, ca);              // ^16
        ca = mul2_(ca, ca);              // ^32
        ca = mul2_(ca, ca);              // ^64
        ar0 = fma2_(ca, wr01, ar0);
        ag0 = fma2_(ca, wg01, ag0);
        ab0 = fma2_(ca, wb01, ab0);

        // pixel 1
        u64 sb = fma2_(bx2, hx01, fma2_(by2, hy01, mul2_(bz2, hz01)));
        mb = max2_s32(mb, sb);
        u64 ub = relu2(sb);
        u64 cb = mul2_(ub, ub);
        cb = mul2_(cb, cb);
        cb = mul2_(cb, cb);
        cb = mul2_(cb, cb);
        cb = mul2_(cb, cb);
        cb = mul2_(cb, cb);
        ar1 = fma2_(cb, wr01, ar1);
        ag1 = fma2_(cb, wg01, ag1);
        ab1 = fma2_(cb, wb01, ab1);
    }

    // unscaled outputs
    float r0, r1, g0, g1, bb0, bb1;
    int ob = b * 3 * HW;
    unpk2(ar0, r0, r1); unpk2(ag0, g0, g1); unpk2(ab0, bb0, bb1);
    out[ob + i0]          = r0 + r1;
    out[ob + HW + i0]     = g0 + g1;
    out[ob + 2 * HW + i0] = bb0 + bb1;
    unpk2(ar1, r0, r1); unpk2(ag1, g0, g1); unpk2(ab1, bb0, bb1);
    out[ob + i1]          = r0 + r1;
    out[ob + HW + i1]     = g0 + g1;
    out[ob + 2 * HW + i1] = bb0 + bb1;

    // global-max reduction (include analytic eh=0 light h=(0,1,1)/sqrt2)
    const float R2I = 0.70710678118654752f;
    float l0, h0, l1, h1;
    unpk2(ma, l0, h0); unpk2(mb, l1, h1);
    float mx = fmaxf(fmaxf(fmaxf(l0, h0), fmaxf(l1, h1)),
                     fmaxf(fmaxf((ay + az) * R2I, (by + bz) * R2I), 0.0f));
    #pragma unroll
    for (int o = 16; o; o >>= 1) mx = fmaxf(mx, __shfl_xor_sync(0xffffffffu, mx, o));
    if ((threadIdx.x & 31) == 0) wm[threadIdx.x >> 5] = mx;
    __syncthreads();
    if (threadIdx.x == 0) {
        float m2 = wm[0];
        #pragma unroll
        for (int i = 1; i < 8; ++i) m2 = fmaxf(m2, wm[i]);
        atomicMax(&g_maxbits, __float_as_uint(m2));  // nonneg bits monotone as uint
    }
}

// ---------------- kernel 2: scale epilogue: out *= 1/gm^64 ----------------
// 4 float4 per thread (MLP=4): grid 384 x 256 threads x 4 tiles = 393216 float4.
__global__ void k_scale(float* __restrict__ out) {
    float gm = __uint_as_float(g_maxbits);
    float g2 = gm * gm;            // ^2
    g2 = g2 * g2;                  // ^4
    g2 = g2 * g2;                  // ^8
    g2 = g2 * g2;                  // ^16
    g2 = g2 * g2;                  // ^32
    g2 = g2 * g2;                  // ^64
    float inv = 1.0f / g2;

    float4* o4 = (float4*)out;
    int base = blockIdx.x * 1024 + threadIdx.x;  // 4 coalesced 256-wide tiles
    float4 v0 = o4[base];
    float4 v1 = o4[base + 256];
    float4 v2 = o4[base + 512];
    float4 v3 = o4[base + 768];
    v0.x *= inv; v0.y *= inv; v0.z *= inv; v0.w *= inv;
    v1.x *= inv; v1.y *= inv; v1.z *= inv; v1.w *= inv;
    v2.x *= inv; v2.y *= inv; v2.z *= inv; v2.w *= inv;
    v3.x *= inv; v3.y *= inv; v3.z *= inv; v3.w *= inv;
    o4[base]       = v0;
    o4[base + 256] = v1;
    o4[base + 512] = v2;
    o4[base + 768] = v3;
}

// ---------------- launch ----------------
extern "C" void kernel_launch(void* const* d_in, const int* in_sizes, int n_in,
                              void* d_out, int out_size) {
    const float* env    = (const float*)d_in[0];
    const float* normal = (const float*)d_in[1];
    if (n_in >= 2 && in_sizes[0] > in_sizes[1]) {
        env    = (const float*)d_in[1];
        normal = (const float*)d_in[0];
    }
    k_setup<<<16, 64>>>(env);
    k_shade<<<dim3(512, 2), 256>>>(normal, (float*)d_out);
    k_scale<<<384, 256>>>((float*)d_out);
}